// round 13
// baseline (speedup 1.0000x reference)
#include <cuda_runtime.h>
#include <cuda_bf16.h>
#include <cstdint>

#define BD 4
#define CD 256
#define HD 56
#define WD 56
#define GD 16
#define GCD 16
#define POSN (BD*HD*WD)   // 12544
#define IN1 2112
#define OUT1 96
#define OWD 112
#define N2 192
#define NROW (BD*HD)      // 224
#define KPGP 72           // padded kp per group (66 real)

// fgemm dynamic smem layout (u32 offsets)
#define ASTRIDE 72                          // A row stride (72 mod 32 = 8)
#define BSTRIDE 104                         // B row stride (104 mod 32 = 8)
#define OFF_AGH 0                           // 72*72 = 5184
#define OFF_AGL (OFF_AGH + KPGP*ASTRIDE)    // 5184
#define OFF_UNI (OFF_AGL + KPGP*ASTRIDE)    // union: taps(8352 f) / B(2*7488 u32)
#define OFF_BGH OFF_UNI
#define OFF_BGL (OFF_UNI + KPGP*BSTRIDE)
#define SM_U32  (OFF_UNI + 2*KPGP*BSTRIDE)  // 25344 u32
#define FG_SMEM (SM_U32 * 4)                // 101376 B

// Scratch (device globals)
__device__ float    g_rp[2ull * POSN * OUT1];
__device__ uint32_t g_w1pth[(size_t)GD * KPGP * OUT1];
__device__ uint32_t g_w1ptl[(size_t)GD * KPGP * OUT1];
__device__ float    g_w23h[(size_t)OUT1 * N2];
__device__ float    g_w23l[(size_t)OUT1 * N2];
__device__ float    g_wab[(size_t)POSN * N2];

// ---------------------------------------------------------------------------
// helpers
// ---------------------------------------------------------------------------
__device__ __forceinline__ uint32_t f2tf32(float f) {
    uint32_t r;
    asm("cvt.rna.tf32.f32 %0, %1;" : "=r"(r) : "f"(f));
    return r;
}
__device__ __forceinline__ void mma_tf32(float* c, const uint32_t* a, const uint32_t* b) {
    asm volatile(
        "mma.sync.aligned.m16n8k8.row.col.f32.tf32.tf32.f32 "
        "{%0,%1,%2,%3}, {%4,%5,%6,%7}, {%8,%9}, {%0,%1,%2,%3};"
        : "+f"(c[0]), "+f"(c[1]), "+f"(c[2]), "+f"(c[3])
        : "r"(a[0]), "r"(a[1]), "r"(a[2]), "r"(a[3]), "r"(b[0]), "r"(b[1]));
}
__device__ __forceinline__ void mma_bf16(float* c, const uint32_t* a, const uint32_t* b) {
    asm volatile(
        "mma.sync.aligned.m16n8k16.row.col.f32.bf16.bf16.f32 "
        "{%0,%1,%2,%3}, {%4,%5,%6,%7}, {%8,%9}, {%0,%1,%2,%3};"
        : "+f"(c[0]), "+f"(c[1]), "+f"(c[2]), "+f"(c[3])
        : "r"(a[0]), "r"(a[1]), "r"(a[2]), "r"(a[3]), "r"(b[0]), "r"(b[1]));
}
__device__ __forceinline__ uint32_t packbf(float klo, float khi) {
    uint32_t r;
    asm("cvt.rn.bf16x2.f32 %0, %1, %2;" : "=r"(r) : "f"(khi), "f"(klo));
    return r;
}
__device__ __forceinline__ float bfround(float v) {
    return __bfloat162float(__float2bfloat16(v));
}

// per-group column map (validated end-to-end in R8/R12)
__device__ __forceinline__ int colmap(int g, int k) {
    if (k < 36)  return g*36 + k;
    if (k < 84)  return 576  + g*48 + (k - 36);
    return 1344 + g*48 + (k - 84);
}

// ---------------------------------------------------------------------------
// K0a: pack per-group-reordered w1 -> bf16x2 hi/lo, [g][kp][n], kp<72 (pad 0)
// ---------------------------------------------------------------------------
__global__ __launch_bounds__(256) void w1pt_kernel(const float* __restrict__ w1) {
    int idx = blockIdx.x * 256 + threadIdx.x;
    if (idx >= GD * KPGP * OUT1) return;
    int n  = idx % OUT1;
    int kp = (idx / OUT1) % KPGP;
    int g  = idx / (OUT1 * KPGP);
    int k0 = 2*kp, k1 = 2*kp + 1;
    float v0 = (k0 < 132) ? w1[(unsigned)n * IN1 + colmap(g, k0)] : 0.f;
    float v1 = (k1 < 132) ? w1[(unsigned)n * IN1 + colmap(g, k1)] : 0.f;
    float h0 = bfround(v0), h1 = bfround(v1);
    g_w1pth[idx] = packbf(h0, h1);
    g_w1ptl[idx] = packbf(v0 - h0, v1 - h1);
}

// ---------------------------------------------------------------------------
// K0b: pre-split [w2|w3] -> [k][n] tf32 hi/lo
// ---------------------------------------------------------------------------
__global__ __launch_bounds__(256) void w23split_kernel(
    const float* __restrict__ w2, const float* __restrict__ w3) {
    int idx = blockIdx.x * 256 + threadIdx.x;
    if (idx >= OUT1 * N2) return;
    int n = idx % N2;
    int k = idx / N2;
    float v = (n < OUT1) ? w2[(unsigned)n * OUT1 + k]
                         : w3[(unsigned)(n - OUT1) * OUT1 + k];
    float h = __uint_as_float(f2tf32(v));
    g_w23h[idx] = h;
    g_w23l[idx] = __uint_as_float(f2tf32(v - h));
}

// ---------------------------------------------------------------------------
// Scrambled-unfold descriptor value from staged taps
// taps layout: [(gc*9 + kw*3 + kh)*58 + wp]
// ---------------------------------------------------------------------------
__device__ __forceinline__ float descval(const float* __restrict__ tp,
                                         int k, int wl,
                                         int jv0, int jv1, int jv2) {
    if (k < 36) {          // x1: max over channels {jc, jc+4, jc+8, jc+12}
        int jc = k / 9, r = k % 9, kh = r / 3, kw = r % 3;
        int jv = (kw == 0) ? jv0 : (kw == 1 ? jv1 : jv2);
        int base = (jc*9 + kw*3 + kh)*58 + wl + jv;
        return fmaxf(fmaxf(tp[base],           tp[base + 4*522]),
                     fmaxf(tp[base + 8*522],   tp[base + 12*522]));
    } else if (k < 84) {   // x2: max over kh
        int kk = k - 36, gc = kk / 3, kw = kk % 3;
        int jv = (kw == 0) ? jv0 : (kw == 1 ? jv1 : jv2);
        int base = (gc*9 + kw*3)*58 + wl + jv;
        return fmaxf(fmaxf(tp[base], tp[base + 58]), tp[base + 116]);
    } else {               // x3: max over kw
        int kk = k - 84, gc = kk / 3, kh = kk % 3;
        int base = (gc*9 + kh)*58 + wl;
        return fmaxf(fmaxf(tp[base + jv0], tp[base + 174 + jv1]),
                     tp[base + 348 + jv2]);
    }
}

// ---------------------------------------------------------------------------
// K1: FUSED descriptor + GEMM1, v2.
// Per group: [taps][sync][D->packed A][sync][B full group][sync][9 MMA chunks,
// NO syncs][sync]. 4 syncs/group vs 19 in v1. 99 KB dyn smem, 2 blocks/SM.
// ---------------------------------------------------------------------------
__global__ __launch_bounds__(256) void fgemm_kernel(const float* __restrict__ x) {
    extern __shared__ uint32_t sm[];
    uint32_t* Agh = sm + OFF_AGH;
    uint32_t* Agl = sm + OFF_AGL;
    uint32_t* Bgh = sm + OFF_BGH;
    uint32_t* Bgl = sm + OFF_BGL;
    float*    taps = reinterpret_cast<float*>(sm + OFF_UNI);

    const int row = blockIdx.x;            // b*56 + h2
    const int half = blockIdx.y;           // groups half*8 .. half*8+7
    const int b = row / HD, h2 = row % HD;
    const int tid  = threadIdx.x;
    const int warp = tid >> 5;
    const int lane = tid & 31;
    const int wm = warp >> 2;              // 0..1 (m)
    const int wn = warp & 3;               // 0..3 (n)
    const int ar = lane >> 2;              // 0..7
    const int ac = lane & 3;               // 0..3
    const unsigned row0 = (unsigned)row * WD;

    const int jv0 = h2 % 3, jv1 = (56 + h2) % 3, jv2 = (112 + h2) % 3;

    // zero A arrays once (pad rows kp>=66 and pad cols m>=56 stay zero)
    for (int i = tid; i < KPGP*ASTRIDE; i += 256) { Agh[i] = 0u; Agl[i] = 0u; }

    float c[2][3][4];
    #pragma unroll
    for (int mt = 0; mt < 2; mt++)
        #pragma unroll
        for (int nt = 0; nt < 3; nt++)
            #pragma unroll
            for (int q = 0; q < 4; q++) c[mt][nt][q] = 0.f;

    for (int gi = 0; gi < 8; gi++) {
        const int g = half*8 + gi;

        // ---- phase 1: stage taps (overwrites B region of prev group) ----
        __syncthreads();
        const unsigned cbase = (unsigned)(b*CD + g*GCD);
        for (int idx = tid; idx < GCD*9*58; idx += 256) {
            int wp = idx % 58;
            int t  = idx / 58;             // gc*9 + kw*3 + kh
            int kh = t % 3;
            int kw = (t / 3) % 3;
            int m  = kw * 56 + h2;
            int hh = m / 3 + kh - 1;
            int ww = wp - 1;
            float v = 0.f;
            if (hh >= 0 && hh < HD && ww >= 0 && ww < WD)
                v = x[((cbase + (unsigned)(t/9))*HD + hh)*WD + ww];
            taps[idx] = v;
        }
        __syncthreads();

        // ---- phase 2: D compute -> packed A (66 kp x 56 m) ----
        for (int idx = tid; idx < 66*56; idx += 256) {
            int m  = idx % 56;
            int kp = idx / 56;
            int k  = 2*kp;
            float v0 = descval(taps, k,   m, jv0, jv1, jv2);
            float v1 = (k + 1 < 132) ? descval(taps, k+1, m, jv0, jv1, jv2) : 0.f;
            float h0 = bfround(v0), h1 = bfround(v1);
            Agh[kp*ASTRIDE + m] = packbf(h0, h1);
            Agl[kp*ASTRIDE + m] = packbf(v0 - h0, v1 - h1);
        }
        __syncthreads();

        // ---- phase 3: B full group (overwrites taps; incl. zero pad rows) ----
        {
            const unsigned base = (unsigned)g * KPGP * OUT1;
            for (int idx = tid; idx < KPGP*OUT1; idx += 256) {
                int n = idx % OUT1, kp = idx / OUT1;
                Bgh[kp*BSTRIDE + n] = g_w1pth[base + idx];
                Bgl[kp*BSTRIDE + n] = g_w1ptl[base + idx];
            }
        }
        __syncthreads();

        // ---- phase 4: 9 MMA chunks, no syncs ----
        for (int ch = 0; ch < 9; ch++) {
            const int kp0 = ch * 8;
            uint32_t ah[2][4], al[2][4];
            #pragma unroll
            for (int mt = 0; mt < 2; mt++) {
                int mrow = wm*32 + mt*16 + ar;
                ah[mt][0] = Agh[(kp0+ac  )*ASTRIDE + mrow];
                ah[mt][1] = Agh[(kp0+ac  )*ASTRIDE + mrow + 8];
                ah[mt][2] = Agh[(kp0+ac+4)*ASTRIDE + mrow];
                ah[mt][3] = Agh[(kp0+ac+4)*ASTRIDE + mrow + 8];
                al[mt][0] = Agl[(kp0+ac  )*ASTRIDE + mrow];
                al[mt][1] = Agl[(kp0+ac  )*ASTRIDE + mrow + 8];
                al[mt][2] = Agl[(kp0+ac+4)*ASTRIDE + mrow];
                al[mt][3] = Agl[(kp0+ac+4)*ASTRIDE + mrow + 8];
            }
            uint32_t bh[3][2], bl[3][2];
            #pragma unroll
            for (int nt = 0; nt < 3; nt++) {
                int n = wn*24 + nt*8 + ar;
                bh[nt][0] = Bgh[(kp0+ac  )*BSTRIDE + n];
                bh[nt][1] = Bgh[(kp0+ac+4)*BSTRIDE + n];
                bl[nt][0] = Bgl[(kp0+ac  )*BSTRIDE + n];
                bl[nt][1] = Bgl[(kp0+ac+4)*BSTRIDE + n];
            }
            #pragma unroll
            for (int mt = 0; mt < 2; mt++)
                #pragma unroll
                for (int nt = 0; nt < 3; nt++) {
                    mma_bf16(c[mt][nt], ah[mt], bl[nt]);
                    mma_bf16(c[mt][nt], al[mt], bh[nt]);
                    mma_bf16(c[mt][nt], ah[mt], bh[nt]);
                }
        }
    }
    __syncthreads();

    // ---- epilogue: store partials, guard local m < 56 ----
    float* rp = &g_rp[(size_t)half * POSN * OUT1];
    #pragma unroll
    for (int nt = 0; nt < 3; nt++) {
        int n0 = wn*24 + nt*8 + 2*ac;
        #pragma unroll
        for (int mt = 0; mt < 2; mt++) {
            int ml = wm*32 + mt*16 + ar;
            if (ml < 56)
                *reinterpret_cast<float2*>(&rp[(row0 + ml)*OUT1 + n0]) =
                    make_float2(c[mt][nt][0], c[mt][nt][1]);
            if (ml + 8 < 56)
                *reinterpret_cast<float2*>(&rp[(row0 + ml + 8)*OUT1 + n0]) =
                    make_float2(c[mt][nt][2], c[mt][nt][3]);
        }
    }
}

// ---------------------------------------------------------------------------
// K2b: GEMM2 (tf32x3, unchanged): wab = relu(BN(rp0+rp1)) @ w23 + bias
// ---------------------------------------------------------------------------
#define GBM 64
#define GBK 16
#define A2STR 72
#define B2STR 200

__global__ __launch_bounds__(256) void gemm2_kernel(
    const float* __restrict__ gamma, const float* __restrict__ beta,
    const float* __restrict__ mean,  const float* __restrict__ var,
    const float* __restrict__ b2,    const float* __restrict__ b3)
{
    __shared__ float A2h[GBK][A2STR], A2l[GBK][A2STR];
    __shared__ float B2h[GBK][B2STR], B2l[GBK][B2STR];
    __shared__ float sS[OUT1], sB[OUT1];

    const int tid  = threadIdx.x;
    const int warp = tid >> 5;
    const int lane = tid & 31;
    const int wm = warp >> 2;
    const int wn = warp & 3;
    const int ar = lane >> 2;
    const int ac = lane & 3;
    const unsigned row0 = blockIdx.x * GBM;

    if (tid < OUT1) {
        float s = gamma[tid] * rsqrtf(var[tid] + 1e-5f);
        sS[tid] = s;
        sB[tid] = beta[tid] - mean[tid] * s;
    }
    __syncthreads();

    float c[2][6][4];
    #pragma unroll
    for (int mt = 0; mt < 2; mt++)
        #pragma unroll
        for (int nt = 0; nt < 6; nt++)
            #pragma unroll
            for (int q = 0; q < 4; q++) c[mt][nt][q] = 0.f;

    const int am = tid >> 2;
    const int akq = tid & 3;

    #pragma unroll
    for (int k0 = 0; k0 < OUT1; k0 += GBK) {
        {
            int kk = k0 + akq*4;
            unsigned base = (row0 + am)*OUT1 + kk;
            float4 p0 = *reinterpret_cast<const float4*>(&g_rp[base]);
            float4 p1 = *reinterpret_cast<const float4*>(&g_rp[(size_t)POSN*OUT1 + base]);
            float v[4] = {p0.x+p1.x, p0.y+p1.y, p0.z+p1.z, p0.w+p1.w};
            #pragma unroll
            for (int i = 0; i < 4; i++) {
                float r = fmaxf(fmaf(v[i], sS[kk+i], sB[kk+i]), 0.f);
                float h = __uint_as_float(f2tf32(r));
                A2h[akq*4 + i][am] = h;
                A2l[akq*4 + i][am] = __uint_as_float(f2tf32(r - h));
            }
        }
        {
            const unsigned base = (unsigned)k0 * N2;
            #pragma unroll
            for (int i = 0; i < 12; i++) {
                int idx = tid + (i << 8);
                int n = idx % N2, k = idx / N2;
                B2h[k][n] = g_w23h[base + idx];
                B2l[k][n] = g_w23l[base + idx];
            }
        }
        __syncthreads();

        #pragma unroll
        for (int ks = 0; ks < 2; ks++) {
            const int kb = ks * 8;
            uint32_t ah[2][4], al[2][4];
            #pragma unroll
            for (int mt = 0; mt < 2; mt++) {
                int mrow = wm*32 + mt*16 + ar;
                ah[mt][0] = __float_as_uint(A2h[kb+ac  ][mrow  ]);
                ah[mt][1] = __float_as_uint(A2h[kb+ac  ][mrow+8]);
                ah[mt][2] = __float_as_uint(A2h[kb+ac+4][mrow  ]);
                ah[mt][3] = __float_as_uint(A2h[kb+ac+4][mrow+8]);
                al[mt][0] = __float_as_uint(A2l[kb+ac  ][mrow  ]);
                al[mt][1] = __float_as_uint(A2l[kb+ac  ][mrow+8]);
                al[mt][2] = __float_as_uint(A2l[kb+ac+4][mrow  ]);
                al[mt][3] = __float_as_uint(A2l[kb+ac+4][mrow+8]);
            }
            uint32_t bh[6][2], bl[6][2];
            #pragma unroll
            for (int nt = 0; nt < 6; nt++) {
                int n = wn*48 + nt*8 + ar;
                bh[nt][0] = __float_as_uint(B2h[kb+ac  ][n]);
                bh[nt][1] = __float_as_uint(B2h[kb+ac+4][n]);
                bl[nt][0] = __float_as_uint(B2l[kb+ac  ][n]);
                bl[nt][1] = __float_as_uint(B2l[kb+ac+4][n]);
            }
            #pragma unroll
            for (int mt = 0; mt < 2; mt++)
                #pragma unroll
                for (int nt = 0; nt < 6; nt++) {
                    mma_tf32(c[mt][nt], ah[mt], bl[nt]);
                    mma_tf32(c[mt][nt], al[mt], bh[nt]);
                    mma_tf32(c[mt][nt], ah[mt], bh[nt]);
                }
        }
        __syncthreads();
    }

    #pragma unroll
    for (int nt = 0; nt < 6; nt++) {
        int n0 = wn*48 + nt*8 + 2*ac;
        float bias0 = (n0 < OUT1) ? b2[n0] : b3[n0 - OUT1];
        float bias1 = (n0 + 1 < OUT1) ? b2[n0 + 1] : b3[n0 + 1 - OUT1];
        #pragma unroll
        for (int mt = 0; mt < 2; mt++) {
            unsigned m0 = row0 + wm*32 + mt*16 + ar;
            *reinterpret_cast<float2*>(&g_wab[(size_t)m0*N2 + n0]) =
                make_float2(c[mt][nt][0] + bias0, c[mt][nt][1] + bias1);
            *reinterpret_cast<float2*>(&g_wab[(size_t)(m0+8)*N2 + n0]) =
                make_float2(c[mt][nt][2] + bias0, c[mt][nt][3] + bias1);
        }
    }
}

// ---------------------------------------------------------------------------
// K3: apply (unchanged)
// ---------------------------------------------------------------------------
__device__ __forceinline__ void load_taps(const float* __restrict__ x,
                                          int b, int g, int h2,
                                          float (*xs)[3][3][58], int tid) {
    const unsigned cbase = (unsigned)(b*CD + g*GCD);
    for (int idx = tid; idx < GCD * 9 * 58; idx += 128) {
        int wp = idx % 58;
        int t  = idx / 58;
        int kh = t % 3;
        int kw = (t / 3) % 3;
        int gc = t / 9;
        int m  = kw * 56 + h2;
        int hh = m / 3 + kh - 1;
        int ww = wp - 1;
        float v = 0.f;
        if (hh >= 0 && hh < HD && ww >= 0 && ww < WD)
            v = x[((cbase + gc)*HD + hh)*WD + ww];
        xs[gc][kw][kh][wp] = v;
    }
}

__global__ __launch_bounds__(128) void apply_kernel(
    const float* __restrict__ x, float* __restrict__ out)
{
    const int g = blockIdx.x, h2 = blockIdx.y, b = blockIdx.z;
    __shared__ float xs[GCD][3][3][58];
    __shared__ float wab[WD][12];
    __shared__ float sms[WD*37];

    const int tid = threadIdx.x;
    const unsigned posBase = (unsigned)(b*HD + h2)*WD;

    for (int it = tid; it < WD * 12; it += 128) {
        int q = it % 12;
        int w = it / 12;
        int col = (q < 6) ? (g*6 + q) : (OUT1 + g*6 + q - 6);
        wab[w][q] = g_wab[(size_t)(posBase + w)*N2 + col];
    }
    load_taps(x, b, g, h2, xs, tid);
    __syncthreads();

    for (int it = tid; it < WD * 4; it += 128) {
        int t = it % 4;
        int w = it / 4;
        int nh = t >> 1, nw = t & 1;
        float e[9], m = -1e30f;
        #pragma unroll
        for (int kk = 0; kk < 9; kk++) {
            int kh = kk / 3, kw = kk % 3;
            e[kk] = wab[w][kh*2 + nh] * wab[w][6 + kw*2 + nw];
            m = fmaxf(m, e[kk]);
        }
        float s = 0.f;
        #pragma unroll
        for (int kk = 0; kk < 9; kk++) { e[kk] = expf(e[kk] - m); s += e[kk]; }
        float inv = 1.f / (s * 9.f);
        #pragma unroll
        for (int kk = 0; kk < 9; kk++) sms[w*37 + t*9 + kk] = e[kk] * inv;
    }
    __syncthreads();

    const int jv0 = h2 % 3, jv1 = (56 + h2) % 3, jv2 = (112 + h2) % 3;
    const int jvv[3] = {jv0, jv1, jv2};

    for (int it = tid; it < GCD * WD; it += 128) {
        int w  = it % WD;
        int gc = it / WD;
        float o[4] = {0.f, 0.f, 0.f, 0.f};
        #pragma unroll
        for (int kk = 0; kk < 9; kk++) {
            int kh = kk / 3, kw = kk % 3;
            float u = xs[gc][kw][kh][w + jvv[kw]];
            #pragma unroll
            for (int t = 0; t < 4; t++)
                o[t] = fmaf(u, sms[w*37 + t*9 + kk], o[t]);
        }
        int c = g*GCD + gc;
        #pragma unroll
        for (int t = 0; t < 4; t++) {
            int nh = t >> 1, nw = t & 1;
            out[(((unsigned)(b*CD + c))*OWD + 2*h2 + nh)*OWD + 2*w + nw] = o[t];
        }
    }
}

// ---------------------------------------------------------------------------
extern "C" void kernel_launch(void* const* d_in, const int* in_sizes, int n_in,
                              void* d_out, int out_size) {
    const float* x     = (const float*)d_in[0];
    const float* w1    = (const float*)d_in[1];
    const float* gamma = (const float*)d_in[2];
    const float* beta  = (const float*)d_in[3];
    const float* mean  = (const float*)d_in[4];
    const float* var   = (const float*)d_in[5];
    const float* w2    = (const float*)d_in[6];
    const float* b2    = (const float*)d_in[7];
    const float* w3    = (const float*)d_in[8];
    const float* b3    = (const float*)d_in[9];
    float* out = (float*)d_out;

    static bool attr_set = false;
    if (!attr_set) {
        cudaFuncSetAttribute(fgemm_kernel,
                             cudaFuncAttributeMaxDynamicSharedMemorySize, FG_SMEM);
        attr_set = true;
    }

    w1pt_kernel<<<(GD*KPGP*OUT1 + 255)/256, 256>>>(w1);
    w23split_kernel<<<(OUT1*N2 + 255)/256, 256>>>(w2, w3);
    fgemm_kernel<<<dim3(NROW, 2), 256, FG_SMEM>>>(x);
    gemm2_kernel<<<POSN / GBM, 256>>>(gamma, beta, mean, var, b2, b3);
    apply_kernel<<<dim3(GD, HD, BD), 128>>>(x, out);
}